// round 8
// baseline (speedup 1.0000x reference)
#include <cuda_runtime.h>
#include <cstdint>

// UnalignmentLoss: min over 17x17 shifts (step 2) of mean L1 between shifted
// x crop and fixed y center crop. x,y: (4,3,256,256) fp32, crop 224x224.
//
// Single fused kernel. One warp per (plane, shift-row i, 4-row chunk); each
// lane owns 8 contiguous output columns. x row staged in smem (swizzled,
// conflict-free STS.128/LDS.v2.b64); 20-pair window streamed through the
// shift loop with lookahead to cap register liveness. Packed f32x2 fma/add;
// abs = 64-bit AND (ALU pipe overlaps FMA pipe). Last block (atomic counter)
// does the 289-way min and resets state.
// (Resubmission of R7 source — previous round died to a broker infra failure.)

#define NS    17
#define W_    256
#define TOLC  16
#define COUNT_F 602112.0f          // 4*3*224*224
#define NBLOCKS (14 * NS * 12)     // 2856

__device__ float g_acc[NS * NS];   // zero at load; last block restores 0
__device__ unsigned g_count;       // zero at load; last block restores 0

// ---- packed f32x2 helpers (uint64_t = b64 carrier) ----
__device__ __forceinline__ uint64_t f2add(uint64_t a, uint64_t b) {
    uint64_t r; asm("add.rn.f32x2 %0, %1, %2;" : "=l"(r) : "l"(a), "l"(b)); return r;
}
__device__ __forceinline__ uint64_t f2fma(uint64_t a, uint64_t b, uint64_t c) {
    uint64_t r; asm("fma.rn.f32x2 %0, %1, %2, %3;" : "=l"(r) : "l"(a), "l"(b), "l"(c)); return r;
}
__device__ __forceinline__ uint64_t f2abs(uint64_t a) {
    return a & 0x7FFFFFFF7FFFFFFFULL;
}
__device__ __forceinline__ void unpack2(uint64_t v, float& lo, float& hi) {
    asm("mov.b64 {%0, %1}, %2;" : "=f"(lo), "=f"(hi) : "l"(v));
}
__device__ __forceinline__ void sts128(unsigned addr, float4 v) {
    asm volatile("st.shared.v4.f32 [%0], {%1,%2,%3,%4};"
                 :: "r"(addr), "f"(v.x), "f"(v.y), "f"(v.z), "f"(v.w));
}
__device__ __forceinline__ void lds_2b64(unsigned addr, uint64_t& a, uint64_t& b) {
    asm volatile("ld.shared.v2.b64 {%0,%1}, [%2];" : "=l"(a), "=l"(b) : "r"(addr));
}
// XOR swizzle on 16B granule index (row = 64 granules): conflict-free for the
// 2-granule staging stores and the 10-granule strided window reads.
__device__ __forceinline__ int swz(int t) { return t ^ ((t >> 3) & 7); }

#define NEG1_X2 0xBF800000BF800000ULL   // packed (-1.0f, -1.0f)

__global__ __launch_bounds__(128, 5) void corr_kernel(const float* __restrict__ x,
                                                      const float* __restrict__ y,
                                                      float* __restrict__ out) {
    const int warp = threadIdx.x >> 5;
    const int lane = threadIdx.x & 31;
    const int bc   = blockIdx.z;       // plane
    const int i    = blockIdx.y;       // shift-row index (shift = 2*i)
    const int r0   = blockIdx.x * 16 + warp * 4;

    const float* xb = x + (size_t)bc * (W_ * W_);
    const float* yb = y + (size_t)bc * (W_ * W_);

    __shared__ __align__(16) float xs[4][2][W_];   // [warp][double-buffer][256]
    __shared__ unsigned s_last;

    const unsigned base = (unsigned)__cvta_generic_to_shared(&xs[warp][0][0]);

    const int Lc = lane < 28 ? lane : 27;          // idle lanes: broadcast reads
    unsigned roff[10];
#pragma unroll
    for (int m = 0; m < 10; m++) roff[m] = (unsigned)(swz(2 * Lc + m) * 16);
    const unsigned s0 = (unsigned)(swz(2 * lane)     * 16);
    const unsigned s1 = (unsigned)(swz(2 * lane + 1) * 16);

    uint64_t acc[NS];
#pragma unroll
    for (int j = 0; j < NS; j++) acc[j] = 0ull;    // +0.0f,+0.0f

    // Prefetch row 0 of x (float4) and y (packed pairs directly).
    const float4* xrow = (const float4*)(xb + (size_t)(2 * i + r0) * W_);
    float4 xa = xrow[2 * lane];
    float4 xc = xrow[2 * lane + 1];
    const ulonglong2* yrow = (const ulonglong2*)(yb + (size_t)(TOLC + r0) * W_ + TOLC);
    ulonglong2 yA = yrow[2 * lane];       // pairs (y0,y1)
    ulonglong2 yB = yrow[2 * lane + 1];   // pairs (y2,y3)

#pragma unroll 1
    for (int rr = 0; rr < 4; rr++) {
        const unsigned boff = (rr & 1) ? (unsigned)(W_ * 4) : 0u;
        sts128(base + boff + s0, xa);
        sts128(base + boff + s1, xc);

        const uint64_t py0 = yA.x, py1 = yA.y, py2 = yB.x, py3 = yB.y;

        if (rr < 3) {   // prefetch next x AND y rows while this row computes
            const float4* xn = (const float4*)(xb + (size_t)(2 * i + r0 + rr + 1) * W_);
            xa = xn[2 * lane];
            xc = xn[2 * lane + 1];
            const ulonglong2* yn =
                (const ulonglong2*)(yb + (size_t)(TOLC + r0 + rr + 1) * W_ + TOLC);
            yA = yn[2 * lane];
            yB = yn[2 * lane + 1];
        }

        __syncwarp();

        // Window pairs [4L, 4L+20) streamed with lookahead.
        uint64_t wd[20];
#pragma unroll
        for (int g = 0; g < 4; g++)   // preload granules 0..3 (pairs 0..7)
            lds_2b64(base + boff + roff[g], wd[2 * g], wd[2 * g + 1]);

#pragma unroll
        for (int j = 0; j < NS; j++) {
            if ((j & 1) == 0 && (j / 2 + 4) < 10) {   // lookahead granule load
                const int g = j / 2 + 4;
                lds_2b64(base + boff + roff[g], wd[2 * g], wd[2 * g + 1]);
            }
            uint64_t a0 = f2abs(f2fma(py0, NEG1_X2, wd[j + 0]));  // |x - y|
            uint64_t a1 = f2abs(f2fma(py1, NEG1_X2, wd[j + 1]));
            uint64_t a2 = f2abs(f2fma(py2, NEG1_X2, wd[j + 2]));
            uint64_t a3 = f2abs(f2fma(py3, NEG1_X2, wd[j + 3]));
            acc[j] = f2add(acc[j], f2add(f2add(a0, a1), f2add(a2, a3)));
        }
    }

    // Reduce: lane j keeps shift-column j's warp sum; idle lanes contribute 0.
    float keep = 0.0f;
#pragma unroll
    for (int j = 0; j < NS; j++) {
        float lo, hi; unpack2(acc[j], lo, hi);
        float v = (lane < 28) ? (lo + hi) : 0.0f;
#pragma unroll
        for (int off = 16; off; off >>= 1) v += __shfl_xor_sync(0xffffffffu, v, off);
        if (lane == j) keep = v;
    }
    if (lane < NS) atomicAdd(&g_acc[i * NS + lane], keep);

    // ---- last-block finalize (threadFenceReduction pattern) ----
    __threadfence();
    if (threadIdx.x == 0) {
        unsigned t = atomicAdd(&g_count, 1u);
        s_last = (t == NBLOCKS - 1) ? 1u : 0u;
    }
    __syncthreads();
    if (s_last && threadIdx.x < 32) {
        volatile float* ga = g_acc;
        float v = 3.4e38f;
        for (int idx = lane; idx < NS * NS; idx += 32) v = fminf(v, ga[idx]);
        for (int idx = lane; idx < NS * NS; idx += 32) g_acc[idx] = 0.0f;  // reset
#pragma unroll
        for (int off = 16; off; off >>= 1)
            v = fminf(v, __shfl_xor_sync(0xffffffffu, v, off));
        if (lane == 0) { out[0] = v * (1.0f / COUNT_F); g_count = 0u; }
    }
}

extern "C" void kernel_launch(void* const* d_in, const int* in_sizes, int n_in,
                              void* d_out, int out_size) {
    (void)in_sizes; (void)n_in; (void)out_size;
    const float* x = (const float*)d_in[0];
    const float* y = (const float*)d_in[1];
    float* out = (float*)d_out;

    dim3 grid(14, NS, 12);
    corr_kernel<<<grid, 128>>>(x, y, out);
}

// round 9
// speedup vs baseline: 1.0530x; 1.0530x over previous
#include <cuda_runtime.h>
#include <cstdint>

// UnalignmentLoss: min over 17x17 shifts (step 2) of mean L1 between shifted
// x crop and fixed y center crop. x,y: (4,3,256,256) fp32, crop 224x224.
//
// Single fused kernel. One warp per (plane, shift-row i, 8-row chunk); each
// lane owns 8 contiguous output columns. x row staged in smem (swizzled,
// conflict-free STS.128/LDS.v2.b64); 20-pair x window streamed through the
// shift loop with lookahead; y loaded as pre-packed f32x2 pairs. Packed f32x2
// fma/add; abs = 64-bit AND (ALU pipe overlaps FMA pipe). 8-row tasks keep
// the reduction epilogue amortized; 5 blocks/SM makes the grid 1.93 waves.
// Last block (atomic counter) does the 289-way min and resets state.

#define NS    17
#define W_    256
#define TOLC  16
#define COUNT_F 602112.0f          // 4*3*224*224
#define NBLOCKS (7 * NS * 12)      // 1428

__device__ float g_acc[NS * NS];   // zero at load; last block restores 0
__device__ unsigned g_count;       // zero at load; last block restores 0

// ---- packed f32x2 helpers (uint64_t = b64 carrier) ----
__device__ __forceinline__ uint64_t f2add(uint64_t a, uint64_t b) {
    uint64_t r; asm("add.rn.f32x2 %0, %1, %2;" : "=l"(r) : "l"(a), "l"(b)); return r;
}
__device__ __forceinline__ uint64_t f2fma(uint64_t a, uint64_t b, uint64_t c) {
    uint64_t r; asm("fma.rn.f32x2 %0, %1, %2, %3;" : "=l"(r) : "l"(a), "l"(b), "l"(c)); return r;
}
__device__ __forceinline__ uint64_t f2abs(uint64_t a) {
    return a & 0x7FFFFFFF7FFFFFFFULL;
}
__device__ __forceinline__ void unpack2(uint64_t v, float& lo, float& hi) {
    asm("mov.b64 {%0, %1}, %2;" : "=f"(lo), "=f"(hi) : "l"(v));
}
__device__ __forceinline__ void sts128(unsigned addr, float4 v) {
    asm volatile("st.shared.v4.f32 [%0], {%1,%2,%3,%4};"
                 :: "r"(addr), "f"(v.x), "f"(v.y), "f"(v.z), "f"(v.w));
}
__device__ __forceinline__ void lds_2b64(unsigned addr, uint64_t& a, uint64_t& b) {
    asm volatile("ld.shared.v2.b64 {%0,%1}, [%2];" : "=l"(a), "=l"(b) : "r"(addr));
}
// XOR swizzle on 16B granule index (row = 64 granules): conflict-free for the
// 2-granule staging stores and the 10-granule strided window reads.
__device__ __forceinline__ int swz(int t) { return t ^ ((t >> 3) & 7); }

#define NEG1_X2 0xBF800000BF800000ULL   // packed (-1.0f, -1.0f)

__global__ __launch_bounds__(128, 5) void corr_kernel(const float* __restrict__ x,
                                                      const float* __restrict__ y,
                                                      float* __restrict__ out) {
    const int warp = threadIdx.x >> 5;
    const int lane = threadIdx.x & 31;
    const int bc   = blockIdx.z;       // plane
    const int i    = blockIdx.y;       // shift-row index (shift = 2*i)
    const int r0   = blockIdx.x * 32 + warp * 8;

    const float* xb = x + (size_t)bc * (W_ * W_);
    const float* yb = y + (size_t)bc * (W_ * W_);

    __shared__ __align__(16) float xs[4][2][W_];   // [warp][double-buffer][256]
    __shared__ unsigned s_last;

    const unsigned base = (unsigned)__cvta_generic_to_shared(&xs[warp][0][0]);

    const int Lc = lane < 28 ? lane : 27;          // idle lanes: broadcast reads
    unsigned roff[10];
#pragma unroll
    for (int m = 0; m < 10; m++) roff[m] = (unsigned)(swz(2 * Lc + m) * 16);
    const unsigned s0 = (unsigned)(swz(2 * lane)     * 16);
    const unsigned s1 = (unsigned)(swz(2 * lane + 1) * 16);

    uint64_t acc[NS];
#pragma unroll
    for (int j = 0; j < NS; j++) acc[j] = 0ull;    // +0.0f,+0.0f

    // Prefetch row 0 of x (float4) and y (pre-packed f32x2 pairs).
    const float4* xrow = (const float4*)(xb + (size_t)(2 * i + r0) * W_);
    float4 xa = xrow[2 * lane];
    float4 xc = xrow[2 * lane + 1];
    const ulonglong2* yrow = (const ulonglong2*)(yb + (size_t)(TOLC + r0) * W_ + TOLC);
    ulonglong2 yA = yrow[2 * lane];       // pairs (y0,y1)
    ulonglong2 yB = yrow[2 * lane + 1];   // pairs (y2,y3)

#pragma unroll 1
    for (int rr = 0; rr < 8; rr++) {
        const unsigned boff = (rr & 1) ? (unsigned)(W_ * 4) : 0u;
        sts128(base + boff + s0, xa);
        sts128(base + boff + s1, xc);

        const uint64_t py0 = yA.x, py1 = yA.y, py2 = yB.x, py3 = yB.y;

        if (rr < 7) {   // prefetch next x AND y rows while this row computes
            const float4* xn = (const float4*)(xb + (size_t)(2 * i + r0 + rr + 1) * W_);
            xa = xn[2 * lane];
            xc = xn[2 * lane + 1];
            const ulonglong2* yn =
                (const ulonglong2*)(yb + (size_t)(TOLC + r0 + rr + 1) * W_ + TOLC);
            yA = yn[2 * lane];
            yB = yn[2 * lane + 1];
        }

        __syncwarp();

        // Window pairs [4L, 4L+20) streamed with lookahead.
        uint64_t wd[20];
#pragma unroll
        for (int g = 0; g < 4; g++)   // preload granules 0..3 (pairs 0..7)
            lds_2b64(base + boff + roff[g], wd[2 * g], wd[2 * g + 1]);

#pragma unroll
        for (int j = 0; j < NS; j++) {
            if ((j & 1) == 0 && (j / 2 + 4) < 10) {   // lookahead granule load
                const int g = j / 2 + 4;
                lds_2b64(base + boff + roff[g], wd[2 * g], wd[2 * g + 1]);
            }
            uint64_t a0 = f2abs(f2fma(py0, NEG1_X2, wd[j + 0]));  // |x - y|
            uint64_t a1 = f2abs(f2fma(py1, NEG1_X2, wd[j + 1]));
            uint64_t a2 = f2abs(f2fma(py2, NEG1_X2, wd[j + 2]));
            uint64_t a3 = f2abs(f2fma(py3, NEG1_X2, wd[j + 3]));
            acc[j] = f2add(acc[j], f2add(f2add(a0, a1), f2add(a2, a3)));
        }
    }

    // Reduce: lane j keeps shift-column j's warp sum; idle lanes contribute 0.
    float keep = 0.0f;
#pragma unroll
    for (int j = 0; j < NS; j++) {
        float lo, hi; unpack2(acc[j], lo, hi);
        float v = (lane < 28) ? (lo + hi) : 0.0f;
#pragma unroll
        for (int off = 16; off; off >>= 1) v += __shfl_xor_sync(0xffffffffu, v, off);
        if (lane == j) keep = v;
    }
    if (lane < NS) atomicAdd(&g_acc[i * NS + lane], keep);

    // ---- last-block finalize (threadFenceReduction pattern) ----
    __threadfence();
    if (threadIdx.x == 0) {
        unsigned t = atomicAdd(&g_count, 1u);
        s_last = (t == NBLOCKS - 1) ? 1u : 0u;
    }
    __syncthreads();
    if (s_last && threadIdx.x < 32) {
        volatile float* ga = g_acc;
        float v = 3.4e38f;
        for (int idx = lane; idx < NS * NS; idx += 32) v = fminf(v, ga[idx]);
        for (int idx = lane; idx < NS * NS; idx += 32) g_acc[idx] = 0.0f;  // reset
#pragma unroll
        for (int off = 16; off; off >>= 1)
            v = fminf(v, __shfl_xor_sync(0xffffffffu, v, off));
        if (lane == 0) { out[0] = v * (1.0f / COUNT_F); g_count = 0u; }
    }
}

extern "C" void kernel_launch(void* const* d_in, const int* in_sizes, int n_in,
                              void* d_out, int out_size) {
    (void)in_sizes; (void)n_in; (void)out_size;
    const float* x = (const float*)d_in[0];
    const float* y = (const float*)d_in[1];
    float* out = (float*)d_out;

    dim3 grid(7, NS, 12);
    corr_kernel<<<grid, 128>>>(x, y, out);
}

// round 10
// speedup vs baseline: 1.0960x; 1.0409x over previous
#include <cuda_runtime.h>
#include <cstdint>

// UnalignmentLoss: min over 17x17 shifts (step 2) of mean L1 between shifted
// x crop and fixed y center crop. x,y: (4,3,256,256) fp32, crop 224x224.
//
// One warp per (plane, shift-row i, 8-row chunk). x rows staged GMEM->SMEM via
// cp.async double-buffer (no staging registers); each lane owns 8 contiguous
// output columns and reads a 40-float window via swizzled conflict-free
// LDS.v2.b64 in two batches. Packed f32x2 fma + 64-bit-AND abs; per-shift sums
// folded into 17 SCALAR accumulators to cut register pressure -> 6 blocks/SM.
// Last block (atomic counter) does the 289-way min and resets state.

#define NS    17
#define W_    256
#define TOLC  16
#define COUNT_F 602112.0f          // 4*3*224*224
#define NBLOCKS (7 * NS * 12)      // 1428

__device__ float g_acc[NS * NS];   // zero at load; last block restores 0
__device__ unsigned g_count;       // zero at load; last block restores 0

// ---- packed f32x2 helpers (uint64_t = b64 carrier) ----
__device__ __forceinline__ uint64_t f2add(uint64_t a, uint64_t b) {
    uint64_t r; asm("add.rn.f32x2 %0, %1, %2;" : "=l"(r) : "l"(a), "l"(b)); return r;
}
__device__ __forceinline__ uint64_t f2fma(uint64_t a, uint64_t b, uint64_t c) {
    uint64_t r; asm("fma.rn.f32x2 %0, %1, %2, %3;" : "=l"(r) : "l"(a), "l"(b), "l"(c)); return r;
}
__device__ __forceinline__ uint64_t f2abs(uint64_t a) {
    return a & 0x7FFFFFFF7FFFFFFFULL;
}
__device__ __forceinline__ void unpack2(uint64_t v, float& lo, float& hi) {
    asm("mov.b64 {%0, %1}, %2;" : "=f"(lo), "=f"(hi) : "l"(v));
}
__device__ __forceinline__ void lds_2b64(unsigned addr, uint64_t& a, uint64_t& b) {
    asm volatile("ld.shared.v2.b64 {%0,%1}, [%2];" : "=l"(a), "=l"(b) : "r"(addr));
}
__device__ __forceinline__ void cp16(unsigned saddr, const float* g) {
    asm volatile("cp.async.ca.shared.global [%0], [%1], 16;"
                 :: "r"(saddr), "l"(g) : "memory");
}
__device__ __forceinline__ void cp_commit() {
    asm volatile("cp.async.commit_group;" ::: "memory");
}
template <int N>
__device__ __forceinline__ void cp_wait() {
    asm volatile("cp.async.wait_group %0;" :: "n"(N) : "memory");
}
// XOR swizzle on 16B granule index (row = 64 granules): conflict-free for the
// 2-granule staging copies and the 10-granule strided window reads.
__device__ __forceinline__ int swz(int t) { return t ^ ((t >> 3) & 7); }

#define NEG1_X2 0xBF800000BF800000ULL   // packed (-1.0f, -1.0f)

__global__ __launch_bounds__(128, 6) void corr_kernel(const float* __restrict__ x,
                                                      const float* __restrict__ y,
                                                      float* __restrict__ out) {
    const int warp = threadIdx.x >> 5;
    const int lane = threadIdx.x & 31;
    const int bc   = blockIdx.z;       // plane
    const int i    = blockIdx.y;       // shift-row index (shift = 2*i)
    const int r0   = blockIdx.x * 32 + warp * 8;

    const float* xb = x + (size_t)bc * (W_ * W_);
    const float* yb = y + (size_t)bc * (W_ * W_);

    __shared__ __align__(16) float xs[4][2][W_];   // [warp][double-buffer][256]
    __shared__ unsigned s_last;

    const unsigned base = (unsigned)__cvta_generic_to_shared(&xs[warp][0][0]);

    const int Lc = lane < 28 ? lane : 27;          // idle lanes: broadcast reads
    unsigned roff[10];
#pragma unroll
    for (int m = 0; m < 10; m++) roff[m] = (unsigned)(swz(2 * Lc + m) * 16);
    const unsigned s0 = (unsigned)(swz(2 * lane)     * 16);
    const unsigned s1 = (unsigned)(swz(2 * lane + 1) * 16);

    float acc[NS];
#pragma unroll
    for (int j = 0; j < NS; j++) acc[j] = 0.0f;

    // Prologue: async-copy x row 0 into buffer 0.
    {
        const float* xr = xb + (size_t)(2 * i + r0) * W_ + 8 * lane;
        cp16(base + s0, xr);
        cp16(base + s1, xr + 4);
        cp_commit();
    }

#pragma unroll 1
    for (int rr = 0; rr < 8; rr++) {
        const unsigned boff  = (rr & 1) ? (unsigned)(W_ * 4) : 0u;
        const unsigned nboff = boff ^ (unsigned)(W_ * 4);

        // Prefetch x row rr+1 (clamped dup on last iter; harmless, in-bounds).
        const int rn = (rr < 7) ? rr + 1 : 7;
        const float* xn = xb + (size_t)(2 * i + r0 + rn) * W_ + 8 * lane;
        cp16(base + nboff + s0, xn);
        cp16(base + nboff + s1, xn + 4);
        cp_commit();

        // y crop row as pre-packed f32x2 pairs (16B-aligned).
        const ulonglong2* yrow =
            (const ulonglong2*)(yb + (size_t)(TOLC + r0 + rr) * W_ + TOLC);
        const ulonglong2 yA = yrow[2 * lane];       // pairs (y0,y1)
        const ulonglong2 yB = yrow[2 * lane + 1];   // pairs (y2,y3)

        cp_wait<1>();       // row rr landed (only row rr+1 still in flight)
        __syncwarp();

        // Window pairs [4L, 4L+20): batch 1 = granules 0..5 (pairs 0..11).
        uint64_t wd[20];
#pragma unroll
        for (int g = 0; g < 6; g++)
            lds_2b64(base + boff + roff[g], wd[2 * g], wd[2 * g + 1]);

#pragma unroll
        for (int j = 0; j < NS; j++) {
            if (j == 5) {   // batch 2 = granules 6..9 (pairs 12..19); 1st use j=9
#pragma unroll
                for (int g = 6; g < 10; g++)
                    lds_2b64(base + boff + roff[g], wd[2 * g], wd[2 * g + 1]);
            }
            uint64_t a0 = f2abs(f2fma(yA.x, NEG1_X2, wd[j + 0]));  // |x - y|
            uint64_t a1 = f2abs(f2fma(yA.y, NEG1_X2, wd[j + 1]));
            uint64_t a2 = f2abs(f2fma(yB.x, NEG1_X2, wd[j + 2]));
            uint64_t a3 = f2abs(f2fma(yB.y, NEG1_X2, wd[j + 3]));
            uint64_t t  = f2add(f2add(a0, a1), f2add(a2, a3));
            float lo, hi; unpack2(t, lo, hi);
            acc[j] += lo + hi;          // scalar accumulator (reg diet)
        }
    }
    cp_wait<0>();   // drain the dup prefetch before exit paths

    // Reduce: lane j keeps shift-column j's warp sum; idle lanes contribute 0.
    float keep = 0.0f;
#pragma unroll
    for (int j = 0; j < NS; j++) {
        float v = (lane < 28) ? acc[j] : 0.0f;
#pragma unroll
        for (int off = 16; off; off >>= 1) v += __shfl_xor_sync(0xffffffffu, v, off);
        if (lane == j) keep = v;
    }
    if (lane < NS) atomicAdd(&g_acc[i * NS + lane], keep);

    // ---- last-block finalize (threadFenceReduction pattern) ----
    __threadfence();
    if (threadIdx.x == 0) {
        unsigned t = atomicAdd(&g_count, 1u);
        s_last = (t == NBLOCKS - 1) ? 1u : 0u;
    }
    __syncthreads();
    if (s_last && threadIdx.x < 32) {
        volatile float* ga = g_acc;
        float v = 3.4e38f;
        for (int idx = lane; idx < NS * NS; idx += 32) v = fminf(v, ga[idx]);
        for (int idx = lane; idx < NS * NS; idx += 32) g_acc[idx] = 0.0f;  // reset
#pragma unroll
        for (int off = 16; off; off >>= 1)
            v = fminf(v, __shfl_xor_sync(0xffffffffu, v, off));
        if (lane == 0) { out[0] = v * (1.0f / COUNT_F); g_count = 0u; }
    }
}

extern "C" void kernel_launch(void* const* d_in, const int* in_sizes, int n_in,
                              void* d_out, int out_size) {
    (void)in_sizes; (void)n_in; (void)out_size;
    const float* x = (const float*)d_in[0];
    const float* y = (const float*)d_in[1];
    float* out = (float*)d_out;

    dim3 grid(7, NS, 12);
    corr_kernel<<<grid, 128>>>(x, y, out);
}

// round 11
// speedup vs baseline: 1.1151x; 1.0174x over previous
#include <cuda_runtime.h>
#include <cstdint>

// UnalignmentLoss: min over 17x17 shifts (step 2) of mean L1 between shifted
// x crop and fixed y center crop. x,y: (4,3,256,256) fp32, crop 224x224.
//
// One warp per (plane, shift-row i, 8-row chunk). BOTH x and y rows staged
// GMEM->SMEM via cp.async double-buffers (no prefetch registers, no in-loop
// LDG latency); swizzled conflict-free LDS.128 reads. Packed f32x2 fma +
// 64-bit-AND abs; 17 scalar accumulators. 6 blocks/SM. Last block (atomic
// counter) does the 289-way min and resets state.

#define NS    17
#define W_    256
#define TOLC  16
#define COUNT_F 602112.0f          // 4*3*224*224
#define NBLOCKS (7 * NS * 12)      // 1428

__device__ float g_acc[NS * NS];   // zero at load; last block restores 0
__device__ unsigned g_count;       // zero at load; last block restores 0

// ---- packed f32x2 helpers (uint64_t = b64 carrier) ----
__device__ __forceinline__ uint64_t f2add(uint64_t a, uint64_t b) {
    uint64_t r; asm("add.rn.f32x2 %0, %1, %2;" : "=l"(r) : "l"(a), "l"(b)); return r;
}
__device__ __forceinline__ uint64_t f2fma(uint64_t a, uint64_t b, uint64_t c) {
    uint64_t r; asm("fma.rn.f32x2 %0, %1, %2, %3;" : "=l"(r) : "l"(a), "l"(b), "l"(c)); return r;
}
__device__ __forceinline__ uint64_t f2abs(uint64_t a) {
    return a & 0x7FFFFFFF7FFFFFFFULL;
}
__device__ __forceinline__ void unpack2(uint64_t v, float& lo, float& hi) {
    asm("mov.b64 {%0, %1}, %2;" : "=f"(lo), "=f"(hi) : "l"(v));
}
__device__ __forceinline__ void lds_2b64(unsigned addr, uint64_t& a, uint64_t& b) {
    asm volatile("ld.shared.v2.b64 {%0,%1}, [%2];" : "=l"(a), "=l"(b) : "r"(addr));
}
__device__ __forceinline__ void cp16(unsigned saddr, const float* g) {
    asm volatile("cp.async.ca.shared.global [%0], [%1], 16;"
                 :: "r"(saddr), "l"(g) : "memory");
}
__device__ __forceinline__ void cp_commit() {
    asm volatile("cp.async.commit_group;" ::: "memory");
}
template <int N>
__device__ __forceinline__ void cp_wait() {
    asm volatile("cp.async.wait_group %0;" :: "n"(N) : "memory");
}
// XOR swizzle on 16B granule index (row = 64 granules): conflict-free for the
// 2-granule staging copies and the strided window reads.
__device__ __forceinline__ int swz(int t) { return t ^ ((t >> 3) & 7); }

#define NEG1_X2 0xBF800000BF800000ULL   // packed (-1.0f, -1.0f)

__global__ __launch_bounds__(128, 6) void corr_kernel(const float* __restrict__ x,
                                                      const float* __restrict__ y,
                                                      float* __restrict__ out) {
    const int warp = threadIdx.x >> 5;
    const int lane = threadIdx.x & 31;
    const int bc   = blockIdx.z;       // plane
    const int i    = blockIdx.y;       // shift-row index (shift = 2*i)
    const int r0   = blockIdx.x * 32 + warp * 8;

    const float* xb = x + (size_t)bc * (W_ * W_);
    const float* yb = y + (size_t)bc * (W_ * W_);

    __shared__ __align__(16) float xs[4][2][W_];   // [warp][double-buffer][256]
    __shared__ __align__(16) float ys[4][2][W_];   // y crop rows (224 used)
    __shared__ unsigned s_last;

    const unsigned xbase = (unsigned)__cvta_generic_to_shared(&xs[warp][0][0]);
    const unsigned ybase = (unsigned)__cvta_generic_to_shared(&ys[warp][0][0]);

    const int Lc = lane < 28 ? lane : 27;          // idle lanes: broadcast reads
    unsigned roff[10];
#pragma unroll
    for (int m = 0; m < 10; m++) roff[m] = (unsigned)(swz(2 * Lc + m) * 16);
    const unsigned s0 = (unsigned)(swz(2 * lane)     * 16);
    const unsigned s1 = (unsigned)(swz(2 * lane + 1) * 16);

    float acc[NS];
#pragma unroll
    for (int j = 0; j < NS; j++) acc[j] = 0.0f;

    // Prologue: async-copy x and y row 0 into buffer 0.
    {
        const float* xr = xb + (size_t)(2 * i + r0) * W_ + 8 * lane;
        cp16(xbase + s0, xr);
        cp16(xbase + s1, xr + 4);
        const float* yr = yb + (size_t)(TOLC + r0) * W_ + TOLC + 8 * lane;
        cp16(ybase + s0, yr);       // lanes 28-31 stage don't-care (in-bounds)
        cp16(ybase + s1, yr + 4);
        cp_commit();
    }

#pragma unroll 1
    for (int rr = 0; rr < 8; rr++) {
        const unsigned boff  = (rr & 1) ? (unsigned)(W_ * 4) : 0u;
        const unsigned nboff = boff ^ (unsigned)(W_ * 4);

        // Prefetch x,y row rr+1 (clamped dup on last iter; harmless, in-bounds).
        const int rn = (rr < 7) ? rr + 1 : 7;
        const float* xn = xb + (size_t)(2 * i + r0 + rn) * W_ + 8 * lane;
        cp16(xbase + nboff + s0, xn);
        cp16(xbase + nboff + s1, xn + 4);
        const float* yn = yb + (size_t)(TOLC + r0 + rn) * W_ + TOLC + 8 * lane;
        cp16(ybase + nboff + s0, yn);
        cp16(ybase + nboff + s1, yn + 4);
        cp_commit();

        cp_wait<1>();       // row rr landed (only row rr+1 still in flight)
        __syncwarp();

        // y pairs for this lane's 8 columns (same swizzled slots it staged).
        uint64_t y0, y1, y2, y3;
        lds_2b64(ybase + boff + s0, y0, y1);
        lds_2b64(ybase + boff + s1, y2, y3);

        // Window pairs [4L, 4L+20): batch 1 = granules 0..5 (pairs 0..11).
        uint64_t wd[20];
#pragma unroll
        for (int g = 0; g < 6; g++)
            lds_2b64(xbase + boff + roff[g], wd[2 * g], wd[2 * g + 1]);

#pragma unroll
        for (int j = 0; j < NS; j++) {
            if (j == 5) {   // batch 2 = granules 6..9 (pairs 12..19); 1st use j=9
#pragma unroll
                for (int g = 6; g < 10; g++)
                    lds_2b64(xbase + boff + roff[g], wd[2 * g], wd[2 * g + 1]);
            }
            uint64_t a0 = f2abs(f2fma(y0, NEG1_X2, wd[j + 0]));  // |x - y|
            uint64_t a1 = f2abs(f2fma(y1, NEG1_X2, wd[j + 1]));
            uint64_t a2 = f2abs(f2fma(y2, NEG1_X2, wd[j + 2]));
            uint64_t a3 = f2abs(f2fma(y3, NEG1_X2, wd[j + 3]));
            uint64_t t  = f2add(f2add(a0, a1), f2add(a2, a3));
            float lo, hi; unpack2(t, lo, hi);
            acc[j] += lo + hi;          // scalar accumulator (reg diet)
        }
    }
    cp_wait<0>();   // drain the dup prefetch before exit paths

    // Reduce: lane j keeps shift-column j's warp sum; idle lanes contribute 0.
    float keep = 0.0f;
#pragma unroll
    for (int j = 0; j < NS; j++) {
        float v = (lane < 28) ? acc[j] : 0.0f;
#pragma unroll
        for (int off = 16; off; off >>= 1) v += __shfl_xor_sync(0xffffffffu, v, off);
        if (lane == j) keep = v;
    }
    if (lane < NS) atomicAdd(&g_acc[i * NS + lane], keep);

    // ---- last-block finalize (threadFenceReduction pattern) ----
    __threadfence();
    if (threadIdx.x == 0) {
        unsigned t = atomicAdd(&g_count, 1u);
        s_last = (t == NBLOCKS - 1) ? 1u : 0u;
    }
    __syncthreads();
    if (s_last && threadIdx.x < 32) {
        volatile float* ga = g_acc;
        float v = 3.4e38f;
        for (int idx = lane; idx < NS * NS; idx += 32) v = fminf(v, ga[idx]);
        for (int idx = lane; idx < NS * NS; idx += 32) g_acc[idx] = 0.0f;  // reset
#pragma unroll
        for (int off = 16; off; off >>= 1)
            v = fminf(v, __shfl_xor_sync(0xffffffffu, v, off));
        if (lane == 0) { out[0] = v * (1.0f / COUNT_F); g_count = 0u; }
    }
}

extern "C" void kernel_launch(void* const* d_in, const int* in_sizes, int n_in,
                              void* d_out, int out_size) {
    (void)in_sizes; (void)n_in; (void)out_size;
    const float* x = (const float*)d_in[0];
    const float* y = (const float*)d_in[1];
    float* out = (float*)d_out;

    dim3 grid(7, NS, 12);
    corr_kernel<<<grid, 128>>>(x, y, out);
}